// round 2
// baseline (speedup 1.0000x reference)
#include <cuda_runtime.h>
#include <cstdint>

// ---------------------------------------------------------------------------
// Problem constants (fixed by the dataset)
// ---------------------------------------------------------------------------
#define N_MOL 200000
#define E_MOL 1000000
#define N_CLQ 120000
#define E_CLQ 500000
#define NG    4096

// ---------------------------------------------------------------------------
// Static device scratch (no allocations allowed anywhere)
// ---------------------------------------------------------------------------
__device__ float g_mh1[(size_t)N_MOL * 156];
__device__ float g_mh2[(size_t)N_MOL * 312];
__device__ float g_magg[(size_t)N_MOL * 156];   // max agg dim for mol branch
__device__ float g_mt [(size_t)N_MOL * 128];
__device__ float g_mh3[(size_t)N_MOL * 128];

__device__ float g_ch1[(size_t)N_CLQ * 184];
__device__ float g_ch2[(size_t)N_CLQ * 368];
__device__ float g_cagg[(size_t)N_CLQ * 184];   // max agg dim for clq branch
__device__ float g_ct [(size_t)N_CLQ * 128];
__device__ float g_ch3[(size_t)N_CLQ * 128];

// ---------------------------------------------------------------------------
// Edge aggregation: agg[dst] += feat[src], vectorized global reductions.
// grid.x covers edges, grid.y covers feature chunks of VEC floats.
// ---------------------------------------------------------------------------
template <int VEC>
__global__ void edge_agg_kernel(const float* __restrict__ feat,
                                const int* __restrict__ src,
                                const int* __restrict__ dst,
                                float* __restrict__ agg,
                                int E, int dim)
{
    int e = blockIdx.x * blockDim.x + threadIdx.x;
    if (e >= E) return;
    int c = blockIdx.y * VEC;
    int s = src[e];
    int d = dst[e];
    const float* p = feat + (size_t)s * dim + c;
    float* q = agg + (size_t)d * dim + c;
    if (VEC == 4) {
        float4 v = *reinterpret_cast<const float4*>(p);
        asm volatile("red.global.add.v4.f32 [%0], {%1,%2,%3,%4};"
                     :: "l"(q), "f"(v.x), "f"(v.y), "f"(v.z), "f"(v.w)
                     : "memory");
    } else {
        float2 v = *reinterpret_cast<const float2*>(p);
        asm volatile("red.global.add.v2.f32 [%0], {%1,%2};"
                     :: "l"(q), "f"(v.x), "f"(v.y)
                     : "memory");
    }
}

// ---------------------------------------------------------------------------
// Fused SAGE GEMM:
//   out = act( A1 @ W1^T  [+ A2 @ W2^T]  [+ Cin]  [+ bias] )
// A*: [N,K] row-major, W*: [O,K] row-major, out/Cin: [N,O].
// Tile 128x128, BK=8, 256 threads, 8x8 per-thread micro-tile.
// smem traffic: 64 B per 64 FFMA per thread = 1.0 B/FFMA (crossbar limit),
// all via conflict-free LDS.128.
// ---------------------------------------------------------------------------
template <bool HAS2, bool HASC, bool BIAS, bool RELU>
__global__ __launch_bounds__(256)
void gemm_kernel(const float* __restrict__ A1, const float* __restrict__ W1,
                 const float* __restrict__ A2, const float* __restrict__ W2,
                 const float* __restrict__ Cin, const float* __restrict__ bias,
                 float* __restrict__ out, int N, int K, int O)
{
    constexpr int BM = 128, BN = 128, BK = 8;
    __shared__ __align__(16) float As[BK][BM];
    __shared__ __align__(16) float Bs[BK][BN];

    const int tid = threadIdx.x;
    const int tx = tid & 15;       // 0..15 -> 8 output cols each
    const int ty = tid >> 4;       // 0..15 -> 8 output rows each
    const int bm0 = blockIdx.y * BM;
    const int bn0 = blockIdx.x * BN;

    float acc[8][8];
#pragma unroll
    for (int m = 0; m < 8; m++)
#pragma unroll
        for (int n = 0; n < 8; n++) acc[m][n] = 0.f;

    const int nsrc = HAS2 ? 2 : 1;
    for (int s = 0; s < nsrc; s++) {
        const float* __restrict__ A = s ? A2 : A1;
        const float* __restrict__ W = s ? W2 : W1;
        for (int k0 = 0; k0 < K; k0 += BK) {
            // load A tile: 128 rows x 8 k = 1024 elems, 4 per thread (transposed store)
#pragma unroll
            for (int i = 0; i < 4; i++) {
                int e = tid + i * 256;
                int r = e >> 3, k = e & 7;
                int gr = bm0 + r, gk = k0 + k;
                As[k][r] = (gr < N && gk < K) ? A[(size_t)gr * K + gk] : 0.f;
            }
            // load W tile: 128 out-rows x 8 k = 1024 elems, 4 per thread
#pragma unroll
            for (int i = 0; i < 4; i++) {
                int e = tid + i * 256;
                int r = e >> 3, k = e & 7;
                int go = bn0 + r, gk = k0 + k;
                Bs[k][r] = (go < O && gk < K) ? W[(size_t)go * K + gk] : 0.f;
            }
            __syncthreads();
#pragma unroll
            for (int k = 0; k < BK; k++) {
                float4 a0 = *reinterpret_cast<const float4*>(&As[k][ty * 8]);
                float4 a1 = *reinterpret_cast<const float4*>(&As[k][ty * 8 + 4]);
                float4 b0 = *reinterpret_cast<const float4*>(&Bs[k][tx * 8]);
                float4 b1 = *reinterpret_cast<const float4*>(&Bs[k][tx * 8 + 4]);
                float av[8] = {a0.x, a0.y, a0.z, a0.w, a1.x, a1.y, a1.z, a1.w};
                float bv[8] = {b0.x, b0.y, b0.z, b0.w, b1.x, b1.y, b1.z, b1.w};
#pragma unroll
                for (int m = 0; m < 8; m++)
#pragma unroll
                    for (int n = 0; n < 8; n++)
                        acc[m][n] = fmaf(av[m], bv[n], acc[m][n]);
            }
            __syncthreads();
        }
    }

    // epilogue
#pragma unroll
    for (int m = 0; m < 8; m++) {
        int row = bm0 + ty * 8 + m;
        if (row >= N) continue;
#pragma unroll
        for (int n = 0; n < 8; n++) {
            int col = bn0 + tx * 8 + n;
            if (col >= O) continue;
            float v = acc[m][n];
            if (BIAS) v += bias[col];
            if (HASC) v += Cin[(size_t)row * O + col];
            if (RELU) v = fmaxf(v, 0.f);
            out[(size_t)row * O + col] = v;
        }
    }
}

// ---------------------------------------------------------------------------
// Global mean pool over sorted batch ids. One block per graph, 128 threads
// (feature dim = 128). Binary-search the node range for graph g.
// ---------------------------------------------------------------------------
__global__ void pool_kernel(const float* __restrict__ h,
                            const int* __restrict__ batch,
                            int N, float* __restrict__ out, int col_off)
{
    int g = blockIdx.x;
    // lower_bound(g)
    int lo = 0, hi = N;
    while (lo < hi) { int mid = (lo + hi) >> 1; if (batch[mid] < g) lo = mid + 1; else hi = mid; }
    int start = lo;
    // lower_bound(g+1)
    hi = N;
    while (lo < hi) { int mid = (lo + hi) >> 1; if (batch[mid] < g + 1) lo = mid + 1; else hi = mid; }
    int end = lo;

    int c = threadIdx.x;
    float s = 0.f;
    for (int r = start; r < end; r++) s += h[(size_t)r * 128 + c];
    float cnt = (end > start) ? (float)(end - start) : 1.f;
    out[(size_t)g * 256 + col_off + c] = s / cnt;
}

// ---------------------------------------------------------------------------
// Host-side branch driver
// ---------------------------------------------------------------------------
static inline dim3 gemm_grid(int N, int O) {
    return dim3((O + 127) / 128, (N + 127) / 128);
}

static void launch_agg(const float* feat, const int* src, const int* dst,
                       float* agg, int N, int E, int dim)
{
    cudaMemsetAsync(agg, 0, (size_t)N * dim * sizeof(float), 0);
    int ebx = (E + 255) / 256;
    if (dim % 4 == 0) {
        dim3 grid(ebx, dim / 4);
        edge_agg_kernel<4><<<grid, 256>>>(feat, src, dst, agg, E, dim);
    } else {
        dim3 grid(ebx, dim / 2);
        edge_agg_kernel<2><<<grid, 256>>>(feat, src, dst, agg, E, dim);
    }
}

static void run_branch(const float* x, const int* ei_src, const int* ei_dst,
                       const int* batch, int N, int E,
                       int d0, int d1, int d2,           // layer in-dims (layer3 out = 128)
                       const float* w1l, const float* b1, const float* w1r,
                       const float* w2l, const float* b2, const float* w2r,
                       const float* w3l, const float* b3, const float* w3r,
                       float* h1, float* h2, float* agg, float* t, float* h3,
                       float* out, int col_off)
{
    // ---- Layer 1: aggregate x (dim d0), fused dual GEMM + bias + relu -> h1 [N,d1]
    launch_agg(x, ei_src, ei_dst, agg, N, E, d0);
    gemm_kernel<true, false, true, true><<<gemm_grid(N, d1), 256>>>(
        agg, w1l, x, w1r, nullptr, b1, h1, N, d0, d1);

    // ---- Layer 2: aggregate h1 (dim d1) -> h2 [N,d2]
    launch_agg(h1, ei_src, ei_dst, agg, N, E, d1);
    gemm_kernel<true, false, true, true><<<gemm_grid(N, d2), 256>>>(
        agg, w2l, h1, w2r, nullptr, b2, h2, N, d1, d2);

    // ---- Layer 3 (transform-first): t = h2 @ w3l^T, aggregate t (dim 128),
    //      h3 = relu(agg + h2 @ w3r^T + b3)
    gemm_kernel<false, false, false, false><<<gemm_grid(N, 128), 256>>>(
        h2, w3l, nullptr, nullptr, nullptr, nullptr, t, N, d2, 128);
    launch_agg(t, ei_src, ei_dst, agg, N, E, 128);
    gemm_kernel<false, true, true, true><<<gemm_grid(N, 128), 256>>>(
        h2, w3r, nullptr, nullptr, agg, b3, h3, N, d2, 128);

    // ---- Global mean pool
    pool_kernel<<<NG, 128>>>(h3, batch, N, out, col_off);
}

extern "C" void kernel_launch(void* const* d_in, const int* in_sizes, int n_in,
                              void* d_out, int out_size)
{
    (void)n_in; (void)out_size; (void)in_sizes;

    const float* x        = (const float*)d_in[0];
    const int*   ei       = (const int*)  d_in[1];   // [2, E_MOL]
    const int*   batch    = (const int*)  d_in[2];
    const float* xc       = (const float*)d_in[3];
    const int*   eic      = (const int*)  d_in[4];   // [2, E_CLQ]
    const int*   batchc   = (const int*)  d_in[5];

    const float* m1_wl = (const float*)d_in[6];
    const float* m1_bl = (const float*)d_in[7];
    const float* m1_wr = (const float*)d_in[8];
    const float* m2_wl = (const float*)d_in[9];
    const float* m2_bl = (const float*)d_in[10];
    const float* m2_wr = (const float*)d_in[11];
    const float* m3_wl = (const float*)d_in[12];
    const float* m3_bl = (const float*)d_in[13];
    const float* m3_wr = (const float*)d_in[14];
    const float* c1_wl = (const float*)d_in[15];
    const float* c1_bl = (const float*)d_in[16];
    const float* c1_wr = (const float*)d_in[17];
    const float* c2_wl = (const float*)d_in[18];
    const float* c2_bl = (const float*)d_in[19];
    const float* c2_wr = (const float*)d_in[20];
    const float* c3_wl = (const float*)d_in[21];
    const float* c3_bl = (const float*)d_in[22];
    const float* c3_wr = (const float*)d_in[23];

    float* out = (float*)d_out;

    float *mh1, *mh2, *magg, *mt, *mh3;
    float *ch1, *ch2, *cagg, *ct, *ch3;
    cudaGetSymbolAddress((void**)&mh1,  g_mh1);
    cudaGetSymbolAddress((void**)&mh2,  g_mh2);
    cudaGetSymbolAddress((void**)&magg, g_magg);
    cudaGetSymbolAddress((void**)&mt,   g_mt);
    cudaGetSymbolAddress((void**)&mh3,  g_mh3);
    cudaGetSymbolAddress((void**)&ch1,  g_ch1);
    cudaGetSymbolAddress((void**)&ch2,  g_ch2);
    cudaGetSymbolAddress((void**)&cagg, g_cagg);
    cudaGetSymbolAddress((void**)&ct,   g_ct);
    cudaGetSymbolAddress((void**)&ch3,  g_ch3);

    // molecule branch: 78 -> 156 -> 312 -> 128, output cols [0,128)
    run_branch(x, ei, ei + E_MOL, batch, N_MOL, E_MOL,
               78, 156, 312,
               m1_wl, m1_bl, m1_wr, m2_wl, m2_bl, m2_wr, m3_wl, m3_bl, m3_wr,
               mh1, mh2, magg, mt, mh3, out, 0);

    // clique branch: 92 -> 184 -> 368 -> 128, output cols [128,256)
    run_branch(xc, eic, eic + E_CLQ, batchc, N_CLQ, E_CLQ,
               92, 184, 368,
               c1_wl, c1_bl, c1_wr, c2_wl, c2_bl, c2_wr, c3_wl, c3_bl, c3_wr,
               ch1, ch2, cagg, ct, ch3, out, 128);
}

// round 3
// speedup vs baseline: 1.7112x; 1.7112x over previous
#include <cuda_runtime.h>
#include <cstdint>

// ---------------------------------------------------------------------------
// Problem constants (fixed by the dataset)
// ---------------------------------------------------------------------------
#define N_MOL 200000
#define E_MOL 1000000
#define N_CLQ 120000
#define E_CLQ 500000
#define NG    4096

// ---------------------------------------------------------------------------
// Static device scratch (no allocations allowed anywhere)
// ---------------------------------------------------------------------------
__device__ float g_mh1[(size_t)N_MOL * 156];
__device__ float g_mh2[(size_t)N_MOL * 312];
__device__ float g_magg[(size_t)N_MOL * 156];   // max agg dim for mol branch
__device__ float g_mt [(size_t)N_MOL * 128];
__device__ float g_mh3[(size_t)N_MOL * 128];

__device__ float g_ch1[(size_t)N_CLQ * 184];
__device__ float g_ch2[(size_t)N_CLQ * 368];
__device__ float g_cagg[(size_t)N_CLQ * 184];   // max agg dim for clq branch
__device__ float g_ct [(size_t)N_CLQ * 128];
__device__ float g_ch3[(size_t)N_CLQ * 128];

// ---------------------------------------------------------------------------
// Edge aggregation: agg[dst] += feat[src], vectorized global reductions.
// ---------------------------------------------------------------------------
template <int VEC>
__global__ void edge_agg_kernel(const float* __restrict__ feat,
                                const int* __restrict__ src,
                                const int* __restrict__ dst,
                                float* __restrict__ agg,
                                int E, int dim)
{
    int e = blockIdx.x * blockDim.x + threadIdx.x;
    if (e >= E) return;
    int c = blockIdx.y * VEC;
    int s = src[e];
    int d = dst[e];
    const float* p = feat + (size_t)s * dim + c;
    float* q = agg + (size_t)d * dim + c;
    if (VEC == 4) {
        float4 v = *reinterpret_cast<const float4*>(p);
        asm volatile("red.global.add.v4.f32 [%0], {%1,%2,%3,%4};"
                     :: "l"(q), "f"(v.x), "f"(v.y), "f"(v.z), "f"(v.w)
                     : "memory");
    } else {
        float2 v = *reinterpret_cast<const float2*>(p);
        asm volatile("red.global.add.v2.f32 [%0], {%1,%2};"
                     :: "l"(q), "f"(v.x), "f"(v.y)
                     : "memory");
    }
}

// ---------------------------------------------------------------------------
// TF32 tensor-core fused SAGE GEMM:
//   out = act( A1 @ W1^T  [+ A2 @ W2^T]  [+ Cin]  [+ bias] )
// A*: [N,K] row-major, W*: [O,K] row-major (== col-major B for mma.row.col).
// Block tile 128x128, BK=16, 256 threads = 8 warps (2 M x 4 N), each warp
// computes 64x32 via 4x4 m16n8k8 HMMA tiles. fp32 accumulation.
// ---------------------------------------------------------------------------
__device__ __forceinline__ uint32_t f32_to_tf32(float v) {
    uint32_t t;
    asm("cvt.rna.tf32.f32 %0, %1;" : "=r"(t) : "f"(v));
    return t;
}

template <bool HAS2, bool HASC, bool BIAS, bool RELU>
__global__ __launch_bounds__(256)
void gemm_kernel(const float* __restrict__ A1, const float* __restrict__ W1,
                 const float* __restrict__ A2, const float* __restrict__ W2,
                 const float* __restrict__ Cin, const float* __restrict__ bias,
                 float* __restrict__ out, int N, int K, int O)
{
    constexpr int BM = 128, BN = 128, BK = 16, PAD = 4;
    __shared__ uint32_t As[BM][BK + PAD];   // [m][k], tf32 bit patterns
    __shared__ uint32_t Ws[BN][BK + PAD];   // [o][k]

    const int tid  = threadIdx.x;
    const int lane = tid & 31;
    const int warp = tid >> 5;
    const int wm   = warp & 1;          // warp row (2)
    const int wn   = warp >> 1;         // warp col (4)
    const int grp  = lane >> 2;         // 0..7
    const int qid  = lane & 3;          // 0..3
    const int bm0  = blockIdx.y * BM;
    const int bn0  = blockIdx.x * BN;

    float acc[4][4][4];                 // [mtile][ntile][frag]
#pragma unroll
    for (int i = 0; i < 4; i++)
#pragma unroll
        for (int j = 0; j < 4; j++)
#pragma unroll
            for (int f = 0; f < 4; f++) acc[i][j][f] = 0.f;

    const int nsrc = HAS2 ? 2 : 1;
    for (int s = 0; s < nsrc; s++) {
        const float* __restrict__ A = s ? A2 : A1;
        const float* __restrict__ W = s ? W2 : W1;
        for (int k0 = 0; k0 < K; k0 += BK) {
            // load + convert A tile: 128x16 = 2048 elems, 8 per thread
#pragma unroll
            for (int i = 0; i < 8; i++) {
                int e = tid + i * 256;
                int r = e >> 4, k = e & 15;
                int gr = bm0 + r, gk = k0 + k;
                float v = (gr < N && gk < K) ? A[(size_t)gr * K + gk] : 0.f;
                As[r][k] = f32_to_tf32(v);
            }
            // load + convert W tile: 128x16
#pragma unroll
            for (int i = 0; i < 8; i++) {
                int e = tid + i * 256;
                int r = e >> 4, k = e & 15;
                int go = bn0 + r, gk = k0 + k;
                float v = (go < O && gk < K) ? W[(size_t)go * K + gk] : 0.f;
                Ws[r][k] = f32_to_tf32(v);
            }
            __syncthreads();

#pragma unroll
            for (int ks = 0; ks < BK; ks += 8) {
                // A fragments: rows wm*64 + i*16 + {grp, grp+8}, cols ks+qid, +4
                uint32_t aF[4][4];
#pragma unroll
                for (int i = 0; i < 4; i++) {
                    int r = wm * 64 + i * 16 + grp;
                    aF[i][0] = As[r    ][ks + qid];
                    aF[i][1] = As[r + 8][ks + qid];
                    aF[i][2] = As[r    ][ks + qid + 4];
                    aF[i][3] = As[r + 8][ks + qid + 4];
                }
                // B fragments: o = wn*32 + j*8 + grp, cols ks+qid, +4
                uint32_t bF[4][2];
#pragma unroll
                for (int j = 0; j < 4; j++) {
                    int o = wn * 32 + j * 8 + grp;
                    bF[j][0] = Ws[o][ks + qid];
                    bF[j][1] = Ws[o][ks + qid + 4];
                }
#pragma unroll
                for (int i = 0; i < 4; i++)
#pragma unroll
                    for (int j = 0; j < 4; j++) {
                        asm volatile(
                            "mma.sync.aligned.m16n8k8.row.col.f32.tf32.tf32.f32 "
                            "{%0,%1,%2,%3}, {%4,%5,%6,%7}, {%8,%9}, {%0,%1,%2,%3};"
                            : "+f"(acc[i][j][0]), "+f"(acc[i][j][1]),
                              "+f"(acc[i][j][2]), "+f"(acc[i][j][3])
                            : "r"(aF[i][0]), "r"(aF[i][1]),
                              "r"(aF[i][2]), "r"(aF[i][3]),
                              "r"(bF[j][0]), "r"(bF[j][1]));
                    }
            }
            __syncthreads();
        }
    }

    // epilogue: c0: (row, col) = (grp, 2*qid); c1: +1 col; c2/c3: row+8
#pragma unroll
    for (int i = 0; i < 4; i++) {
        int row0 = bm0 + wm * 64 + i * 16 + grp;
#pragma unroll
        for (int j = 0; j < 4; j++) {
            int col0 = bn0 + wn * 32 + j * 8 + qid * 2;
#pragma unroll
            for (int h = 0; h < 2; h++) {      // h=0: rows row0, h=1: row0+8
                int row = row0 + h * 8;
                if (row >= N) continue;
#pragma unroll
                for (int g = 0; g < 2; g++) {  // 2 adjacent cols
                    int col = col0 + g;
                    if (col >= O) continue;
                    float v = acc[i][j][h * 2 + g];
                    if (BIAS) v += bias[col];
                    if (HASC) v += Cin[(size_t)row * O + col];
                    if (RELU) v = fmaxf(v, 0.f);
                    out[(size_t)row * O + col] = v;
                }
            }
        }
    }
}

// ---------------------------------------------------------------------------
// Global mean pool over sorted batch ids. One block per graph, 128 threads.
// ---------------------------------------------------------------------------
__global__ void pool_kernel(const float* __restrict__ h,
                            const int* __restrict__ batch,
                            int N, float* __restrict__ out, int col_off)
{
    int g = blockIdx.x;
    int lo = 0, hi = N;
    while (lo < hi) { int mid = (lo + hi) >> 1; if (batch[mid] < g) lo = mid + 1; else hi = mid; }
    int start = lo;
    hi = N;
    while (lo < hi) { int mid = (lo + hi) >> 1; if (batch[mid] < g + 1) lo = mid + 1; else hi = mid; }
    int end = lo;

    int c = threadIdx.x;
    float s = 0.f;
    for (int r = start; r < end; r++) s += h[(size_t)r * 128 + c];
    float cnt = (end > start) ? (float)(end - start) : 1.f;
    out[(size_t)g * 256 + col_off + c] = s / cnt;
}

// ---------------------------------------------------------------------------
// Host-side drivers
// ---------------------------------------------------------------------------
static inline dim3 gemm_grid(int N, int O) {
    return dim3((O + 127) / 128, (N + 127) / 128);
}

static void launch_agg(const float* feat, const int* src, const int* dst,
                       float* agg, int N, int E, int dim)
{
    cudaMemsetAsync(agg, 0, (size_t)N * dim * sizeof(float), 0);
    int ebx = (E + 255) / 256;
    if (dim % 4 == 0) {
        dim3 grid(ebx, dim / 4);
        edge_agg_kernel<4><<<grid, 256>>>(feat, src, dst, agg, E, dim);
    } else {
        dim3 grid(ebx, dim / 2);
        edge_agg_kernel<2><<<grid, 256>>>(feat, src, dst, agg, E, dim);
    }
}

static void run_branch(const float* x, const int* ei_src, const int* ei_dst,
                       const int* batch, int N, int E,
                       int d0, int d1, int d2,
                       const float* w1l, const float* b1, const float* w1r,
                       const float* w2l, const float* b2, const float* w2r,
                       const float* w3l, const float* b3, const float* w3r,
                       float* h1, float* h2, float* agg, float* t, float* h3,
                       float* out, int col_off)
{
    // Layer 1: aggregate x (dim d0), fused dual GEMM + bias + relu -> h1 [N,d1]
    launch_agg(x, ei_src, ei_dst, agg, N, E, d0);
    gemm_kernel<true, false, true, true><<<gemm_grid(N, d1), 256>>>(
        agg, w1l, x, w1r, nullptr, b1, h1, N, d0, d1);

    // Layer 2: aggregate h1 (dim d1) -> h2 [N,d2]
    launch_agg(h1, ei_src, ei_dst, agg, N, E, d1);
    gemm_kernel<true, false, true, true><<<gemm_grid(N, d2), 256>>>(
        agg, w2l, h1, w2r, nullptr, b2, h2, N, d1, d2);

    // Layer 3 (transform-first): t = h2 @ w3l^T, aggregate t (dim 128),
    // h3 = relu(agg + h2 @ w3r^T + b3)
    gemm_kernel<false, false, false, false><<<gemm_grid(N, 128), 256>>>(
        h2, w3l, nullptr, nullptr, nullptr, nullptr, t, N, d2, 128);
    launch_agg(t, ei_src, ei_dst, agg, N, E, 128);
    gemm_kernel<false, true, true, true><<<gemm_grid(N, 128), 256>>>(
        h2, w3r, nullptr, nullptr, agg, b3, h3, N, d2, 128);

    // Global mean pool
    pool_kernel<<<NG, 128>>>(h3, batch, N, out, col_off);
}

extern "C" void kernel_launch(void* const* d_in, const int* in_sizes, int n_in,
                              void* d_out, int out_size)
{
    (void)n_in; (void)out_size; (void)in_sizes;

    const float* x        = (const float*)d_in[0];
    const int*   ei       = (const int*)  d_in[1];   // [2, E_MOL]
    const int*   batch    = (const int*)  d_in[2];
    const float* xc       = (const float*)d_in[3];
    const int*   eic      = (const int*)  d_in[4];   // [2, E_CLQ]
    const int*   batchc   = (const int*)  d_in[5];

    const float* m1_wl = (const float*)d_in[6];
    const float* m1_bl = (const float*)d_in[7];
    const float* m1_wr = (const float*)d_in[8];
    const float* m2_wl = (const float*)d_in[9];
    const float* m2_bl = (const float*)d_in[10];
    const float* m2_wr = (const float*)d_in[11];
    const float* m3_wl = (const float*)d_in[12];
    const float* m3_bl = (const float*)d_in[13];
    const float* m3_wr = (const float*)d_in[14];
    const float* c1_wl = (const float*)d_in[15];
    const float* c1_bl = (const float*)d_in[16];
    const float* c1_wr = (const float*)d_in[17];
    const float* c2_wl = (const float*)d_in[18];
    const float* c2_bl = (const float*)d_in[19];
    const float* c2_wr = (const float*)d_in[20];
    const float* c3_wl = (const float*)d_in[21];
    const float* c3_bl = (const float*)d_in[22];
    const float* c3_wr = (const float*)d_in[23];

    float* out = (float*)d_out;

    float *mh1, *mh2, *magg, *mt, *mh3;
    float *ch1, *ch2, *cagg, *ct, *ch3;
    cudaGetSymbolAddress((void**)&mh1,  g_mh1);
    cudaGetSymbolAddress((void**)&mh2,  g_mh2);
    cudaGetSymbolAddress((void**)&magg, g_magg);
    cudaGetSymbolAddress((void**)&mt,   g_mt);
    cudaGetSymbolAddress((void**)&mh3,  g_mh3);
    cudaGetSymbolAddress((void**)&ch1,  g_ch1);
    cudaGetSymbolAddress((void**)&ch2,  g_ch2);
    cudaGetSymbolAddress((void**)&cagg, g_cagg);
    cudaGetSymbolAddress((void**)&ct,   g_ct);
    cudaGetSymbolAddress((void**)&ch3,  g_ch3);

    // molecule branch: 78 -> 156 -> 312 -> 128, output cols [0,128)
    run_branch(x, ei, ei + E_MOL, batch, N_MOL, E_MOL,
               78, 156, 312,
               m1_wl, m1_bl, m1_wr, m2_wl, m2_bl, m2_wr, m3_wl, m3_bl, m3_wr,
               mh1, mh2, magg, mt, mh3, out, 0);

    // clique branch: 92 -> 184 -> 368 -> 128, output cols [128,256)
    run_branch(xc, eic, eic + E_CLQ, batchc, N_CLQ, E_CLQ,
               92, 184, 368,
               c1_wl, c1_bl, c1_wr, c2_wl, c2_bl, c2_wr, c3_wl, c3_bl, c3_wr,
               ch1, ch2, cagg, ct, ch3, out, 128);
}

// round 4
// speedup vs baseline: 2.7542x; 1.6096x over previous
#include <cuda_runtime.h>
#include <cstdint>

// ---------------------------------------------------------------------------
// Problem constants (fixed by the dataset)
// ---------------------------------------------------------------------------
#define N_MOL 200000
#define E_MOL 1000000
#define N_CLQ 120000
#define E_CLQ 500000
#define NG    4096

// ---------------------------------------------------------------------------
// Static device scratch (no allocations allowed anywhere)
// ---------------------------------------------------------------------------
__device__ float g_mh1[(size_t)N_MOL * 156];
__device__ float g_mh2[(size_t)N_MOL * 312];
__device__ float g_magg[(size_t)N_MOL * 156];
__device__ float g_mt [(size_t)N_MOL * 128];
__device__ float g_mh3[(size_t)N_MOL * 128];

__device__ float g_ch1[(size_t)N_CLQ * 184];
__device__ float g_ch2[(size_t)N_CLQ * 368];
__device__ float g_cagg[(size_t)N_CLQ * 184];
__device__ float g_ct [(size_t)N_CLQ * 128];
__device__ float g_ch3[(size_t)N_CLQ * 128];

// tf32-converted weights (12 matrices, 465040 elements total)
__device__ uint32_t g_wtf32[470000];

__device__ __forceinline__ uint32_t f32_to_tf32(float v) {
    uint32_t t;
    asm("cvt.rna.tf32.f32 %0, %1;" : "=r"(t) : "f"(v));
    return t;
}

// ---------------------------------------------------------------------------
// Weight pre-conversion: f32 -> tf32 bit patterns (run once per launch)
// ---------------------------------------------------------------------------
__global__ void cvt_tf32_kernel(const float* __restrict__ in,
                                uint32_t* __restrict__ out, int n)
{
    int i = blockIdx.x * blockDim.x + threadIdx.x;
    if (i < n) out[i] = f32_to_tf32(in[i]);
}

// ---------------------------------------------------------------------------
// Edge aggregation, warp-per-edge: indices loaded once, lanes sweep the
// feature row with coalesced vector loads + red.global.add.
// ---------------------------------------------------------------------------
template <int VEC>
__global__ void edge_agg_warp(const float* __restrict__ feat,
                              const int* __restrict__ src,
                              const int* __restrict__ dst,
                              float* __restrict__ agg,
                              int E, int dim)
{
    int w = blockIdx.x * 8 + (threadIdx.x >> 5);
    if (w >= E) return;
    int lane = threadIdx.x & 31;
    int s = __ldg(src + w);
    int d = __ldg(dst + w);
    const float* p = feat + (size_t)s * dim;
    float* q = agg + (size_t)d * dim;
    int chunks = dim / VEC;
    for (int c = lane; c < chunks; c += 32) {
        if (VEC == 4) {
            float4 v = *reinterpret_cast<const float4*>(p + c * 4);
            asm volatile("red.global.add.v4.f32 [%0], {%1,%2,%3,%4};"
                         :: "l"(q + c * 4), "f"(v.x), "f"(v.y), "f"(v.z), "f"(v.w)
                         : "memory");
        } else {
            float2 v = *reinterpret_cast<const float2*>(p + c * 2);
            asm volatile("red.global.add.v2.f32 [%0], {%1,%2};"
                         :: "l"(q + c * 2), "f"(v.x), "f"(v.y)
                         : "memory");
        }
    }
}

// ---------------------------------------------------------------------------
// TF32 tensor-core fused SAGE GEMM, register-pipelined staging:
//   out = act( A1 @ W1^T  [+ A2 @ W2^T]  [+ Cin]  [+ bias] )
// A*: [N,K] f32 row-major; W*: [O,K] tf32 row-major (pre-converted).
// Block tile 128x128, BK=16, 256 threads = 8 warps (2M x 4N), each warp
// 64x32 via 4x4 m16n8k8 tf32 MMA tiles, fp32 accumulation.
// ---------------------------------------------------------------------------
template <int VEC, bool HAS2, bool HASC, bool BIAS, bool RELU>
__global__ __launch_bounds__(256, 2)
void gemm_kernel(const float* __restrict__ A1, const uint32_t* __restrict__ W1,
                 const float* __restrict__ A2, const uint32_t* __restrict__ W2,
                 const float* __restrict__ Cin, const float* __restrict__ bias,
                 float* __restrict__ out, int N, int K, int O)
{
    constexpr int BM = 128, BN = 128, BK = 16, SW = 20;
    __shared__ uint32_t As[BM][SW];
    __shared__ uint32_t Ws[BN][SW];

    const int tid  = threadIdx.x;
    const int lane = tid & 31;
    const int warp = tid >> 5;
    const int wm   = warp & 1;
    const int wn   = warp >> 1;
    const int grp  = lane >> 2;
    const int qid  = lane & 3;
    const int bm0  = blockIdx.y * BM;
    const int bn0  = blockIdx.x * BN;

    const int nk = (K + BK - 1) / BK;
    const int T  = (HAS2 ? 2 : 1) * nk;

    float    regA[8];
    uint32_t regW[8];

    auto prefetch = [&](int t) {
        const float*    A;
        const uint32_t* W;
        int k0;
        if (HAS2 && t >= nk) { A = A2; W = W2; k0 = (t - nk) * BK; }
        else                 { A = A1; W = W1; k0 = t * BK; }
        if (VEC == 4) {
#pragma unroll
            for (int i = 0; i < 2; i++) {
                int r = (tid >> 2) + i * 64;
                int k = (tid & 3) * 4;
                bool ok = (k0 + k) < K;          // K % 4 == 0: chunk fully valid or fully out
                int gr = min(bm0 + r, N - 1);
                int go = min(bn0 + r, O - 1);
                float4 va = ok ? *reinterpret_cast<const float4*>(A + (size_t)gr * K + k0 + k)
                               : make_float4(0.f, 0.f, 0.f, 0.f);
                uint4  vw = ok ? *reinterpret_cast<const uint4*>(W + (size_t)go * K + k0 + k)
                               : make_uint4(0u, 0u, 0u, 0u);
                regA[i*4+0] = va.x; regA[i*4+1] = va.y; regA[i*4+2] = va.z; regA[i*4+3] = va.w;
                regW[i*4+0] = vw.x; regW[i*4+1] = vw.y; regW[i*4+2] = vw.z; regW[i*4+3] = vw.w;
            }
        } else {
#pragma unroll
            for (int i = 0; i < 4; i++) {
                int r = (tid >> 3) + i * 32;
                int k = (tid & 7) * 2;
                bool ok = (k0 + k) < K;          // K % 2 == 0
                int gr = min(bm0 + r, N - 1);
                int go = min(bn0 + r, O - 1);
                float2 va = ok ? *reinterpret_cast<const float2*>(A + (size_t)gr * K + k0 + k)
                               : make_float2(0.f, 0.f);
                uint2  vw = ok ? *reinterpret_cast<const uint2*>(W + (size_t)go * K + k0 + k)
                               : make_uint2(0u, 0u);
                regA[i*2+0] = va.x; regA[i*2+1] = va.y;
                regW[i*2+0] = vw.x; regW[i*2+1] = vw.y;
            }
        }
    };

    auto commit = [&]() {
        if (VEC == 4) {
#pragma unroll
            for (int i = 0; i < 2; i++) {
                int r = (tid >> 2) + i * 64;
                int k = (tid & 3) * 4;
                uint4 ua = make_uint4(f32_to_tf32(regA[i*4+0]), f32_to_tf32(regA[i*4+1]),
                                      f32_to_tf32(regA[i*4+2]), f32_to_tf32(regA[i*4+3]));
                *reinterpret_cast<uint4*>(&As[r][k]) = ua;
                *reinterpret_cast<uint4*>(&Ws[r][k]) =
                    make_uint4(regW[i*4+0], regW[i*4+1], regW[i*4+2], regW[i*4+3]);
            }
        } else {
#pragma unroll
            for (int i = 0; i < 4; i++) {
                int r = (tid >> 3) + i * 32;
                int k = (tid & 7) * 2;
                *reinterpret_cast<uint2*>(&As[r][k]) =
                    make_uint2(f32_to_tf32(regA[i*2+0]), f32_to_tf32(regA[i*2+1]));
                *reinterpret_cast<uint2*>(&Ws[r][k]) = make_uint2(regW[i*2+0], regW[i*2+1]);
            }
        }
    };

    float acc[4][4][4];
#pragma unroll
    for (int i = 0; i < 4; i++)
#pragma unroll
        for (int j = 0; j < 4; j++)
#pragma unroll
            for (int f = 0; f < 4; f++) acc[i][j][f] = 0.f;

    prefetch(0);
    for (int t = 0; t < T; t++) {
        __syncthreads();
        commit();
        __syncthreads();
        if (t + 1 < T) prefetch(t + 1);   // overlaps the MMA work below

#pragma unroll
        for (int ks = 0; ks < BK; ks += 8) {
            uint32_t aF[4][4];
#pragma unroll
            for (int i = 0; i < 4; i++) {
                int r = wm * 64 + i * 16 + grp;
                aF[i][0] = As[r    ][ks + qid];
                aF[i][1] = As[r + 8][ks + qid];
                aF[i][2] = As[r    ][ks + qid + 4];
                aF[i][3] = As[r + 8][ks + qid + 4];
            }
            uint32_t bF[4][2];
#pragma unroll
            for (int j = 0; j < 4; j++) {
                int o = wn * 32 + j * 8 + grp;
                bF[j][0] = Ws[o][ks + qid];
                bF[j][1] = Ws[o][ks + qid + 4];
            }
#pragma unroll
            for (int i = 0; i < 4; i++)
#pragma unroll
                for (int j = 0; j < 4; j++) {
                    asm volatile(
                        "mma.sync.aligned.m16n8k8.row.col.f32.tf32.tf32.f32 "
                        "{%0,%1,%2,%3}, {%4,%5,%6,%7}, {%8,%9}, {%0,%1,%2,%3};"
                        : "+f"(acc[i][j][0]), "+f"(acc[i][j][1]),
                          "+f"(acc[i][j][2]), "+f"(acc[i][j][3])
                        : "r"(aF[i][0]), "r"(aF[i][1]),
                          "r"(aF[i][2]), "r"(aF[i][3]),
                          "r"(bF[j][0]), "r"(bF[j][1]));
                }
        }
    }

    // epilogue (float2 stores; O is always even, col0 is even)
#pragma unroll
    for (int i = 0; i < 4; i++) {
        int row0 = bm0 + wm * 64 + i * 16 + grp;
#pragma unroll
        for (int j = 0; j < 4; j++) {
            int col0 = bn0 + wn * 32 + j * 8 + qid * 2;
            if (col0 >= O) continue;
            float2 bv;
            if (BIAS) bv = *reinterpret_cast<const float2*>(bias + col0);
#pragma unroll
            for (int h = 0; h < 2; h++) {
                int row = row0 + h * 8;
                if (row >= N) continue;
                float v0 = acc[i][j][h * 2 + 0];
                float v1 = acc[i][j][h * 2 + 1];
                if (BIAS) { v0 += bv.x; v1 += bv.y; }
                if (HASC) {
                    float2 cv = *reinterpret_cast<const float2*>(Cin + (size_t)row * O + col0);
                    v0 += cv.x; v1 += cv.y;
                }
                if (RELU) { v0 = fmaxf(v0, 0.f); v1 = fmaxf(v1, 0.f); }
                *reinterpret_cast<float2*>(out + (size_t)row * O + col0) = make_float2(v0, v1);
            }
        }
    }
}

// ---------------------------------------------------------------------------
// Global mean pool over sorted batch ids. One block per graph, 128 threads.
// ---------------------------------------------------------------------------
__global__ void pool_kernel(const float* __restrict__ h,
                            const int* __restrict__ batch,
                            int N, float* __restrict__ out, int col_off)
{
    int g = blockIdx.x;
    int lo = 0, hi = N;
    while (lo < hi) { int mid = (lo + hi) >> 1; if (batch[mid] < g) lo = mid + 1; else hi = mid; }
    int start = lo;
    hi = N;
    while (lo < hi) { int mid = (lo + hi) >> 1; if (batch[mid] < g + 1) lo = mid + 1; else hi = mid; }
    int end = lo;

    int c = threadIdx.x;
    float s = 0.f;
    for (int r = start; r < end; r++) s += h[(size_t)r * 128 + c];
    float cnt = (end > start) ? (float)(end - start) : 1.f;
    out[(size_t)g * 256 + col_off + c] = s / cnt;
}

// ---------------------------------------------------------------------------
// Host-side drivers
// ---------------------------------------------------------------------------
static inline dim3 gemm_grid(int N, int O) {
    return dim3((O + 127) / 128, (N + 127) / 128);
}

static void launch_agg(const float* feat, const int* src, const int* dst,
                       float* agg, int N, int E, int dim)
{
    cudaMemsetAsync(agg, 0, (size_t)N * dim * sizeof(float), 0);
    int blocks = (E + 7) / 8;          // 8 warps (edges) per 256-thread block
    if (dim % 4 == 0) edge_agg_warp<4><<<blocks, 256>>>(feat, src, dst, agg, E, dim);
    else              edge_agg_warp<2><<<blocks, 256>>>(feat, src, dst, agg, E, dim);
}

static void run_branch(const float* x, const int* ei_src, const int* ei_dst,
                       const int* batch, int N, int E,
                       int d0, int d1, int d2,
                       const uint32_t* w1l, const float* b1, const uint32_t* w1r,
                       const uint32_t* w2l, const float* b2, const uint32_t* w2r,
                       const uint32_t* w3l, const float* b3, const uint32_t* w3r,
                       float* h1, float* h2, float* agg, float* t, float* h3,
                       float* out, int col_off)
{
    // Layer 1: aggregate x (dim d0), fused dual GEMM + bias + relu -> h1 [N,d1]
    launch_agg(x, ei_src, ei_dst, agg, N, E, d0);
    if (d0 % 4 == 0)
        gemm_kernel<4, true, false, true, true><<<gemm_grid(N, d1), 256>>>(
            agg, w1l, x, w1r, nullptr, b1, h1, N, d0, d1);
    else
        gemm_kernel<2, true, false, true, true><<<gemm_grid(N, d1), 256>>>(
            agg, w1l, x, w1r, nullptr, b1, h1, N, d0, d1);

    // Layer 2: aggregate h1 (dim d1) -> h2 [N,d2]
    launch_agg(h1, ei_src, ei_dst, agg, N, E, d1);
    gemm_kernel<4, true, false, true, true><<<gemm_grid(N, d2), 256>>>(
        agg, w2l, h1, w2r, nullptr, b2, h2, N, d1, d2);

    // Layer 3 (transform-first): t = h2 @ w3l^T, aggregate t (dim 128),
    // h3 = relu(agg + h2 @ w3r^T + b3)
    gemm_kernel<4, false, false, false, false><<<gemm_grid(N, 128), 256>>>(
        h2, w3l, nullptr, nullptr, nullptr, nullptr, t, N, d2, 128);
    launch_agg(t, ei_src, ei_dst, agg, N, E, 128);
    gemm_kernel<4, false, true, true, true><<<gemm_grid(N, 128), 256>>>(
        h2, w3r, nullptr, nullptr, agg, b3, h3, N, d2, 128);

    // Global mean pool
    pool_kernel<<<NG, 128>>>(h3, batch, N, out, col_off);
}

extern "C" void kernel_launch(void* const* d_in, const int* in_sizes, int n_in,
                              void* d_out, int out_size)
{
    (void)n_in; (void)out_size; (void)in_sizes;

    const float* x        = (const float*)d_in[0];
    const int*   ei       = (const int*)  d_in[1];
    const int*   batch    = (const int*)  d_in[2];
    const float* xc       = (const float*)d_in[3];
    const int*   eic      = (const int*)  d_in[4];
    const int*   batchc   = (const int*)  d_in[5];

    const float* wsrc[12] = {
        (const float*)d_in[6],  (const float*)d_in[8],    // m1_wl, m1_wr
        (const float*)d_in[9],  (const float*)d_in[11],   // m2_wl, m2_wr
        (const float*)d_in[12], (const float*)d_in[14],   // m3_wl, m3_wr
        (const float*)d_in[15], (const float*)d_in[17],   // c1_wl, c1_wr
        (const float*)d_in[18], (const float*)d_in[20],   // c2_wl, c2_wr
        (const float*)d_in[21], (const float*)d_in[23],   // c3_wl, c3_wr
    };
    const int wcnt[12] = {
        156*78, 156*78, 312*156, 312*156, 128*312, 128*312,
        184*92, 184*92, 368*184, 368*184, 128*368, 128*368
    };
    const float* m1_bl = (const float*)d_in[7];
    const float* m2_bl = (const float*)d_in[10];
    const float* m3_bl = (const float*)d_in[13];
    const float* c1_bl = (const float*)d_in[16];
    const float* c2_bl = (const float*)d_in[19];
    const float* c3_bl = (const float*)d_in[22];

    float* out = (float*)d_out;

    float *mh1, *mh2, *magg, *mt, *mh3;
    float *ch1, *ch2, *cagg, *ct, *ch3;
    uint32_t* wt;
    cudaGetSymbolAddress((void**)&mh1,  g_mh1);
    cudaGetSymbolAddress((void**)&mh2,  g_mh2);
    cudaGetSymbolAddress((void**)&magg, g_magg);
    cudaGetSymbolAddress((void**)&mt,   g_mt);
    cudaGetSymbolAddress((void**)&mh3,  g_mh3);
    cudaGetSymbolAddress((void**)&ch1,  g_ch1);
    cudaGetSymbolAddress((void**)&ch2,  g_ch2);
    cudaGetSymbolAddress((void**)&cagg, g_cagg);
    cudaGetSymbolAddress((void**)&ct,   g_ct);
    cudaGetSymbolAddress((void**)&ch3,  g_ch3);
    cudaGetSymbolAddress((void**)&wt,   g_wtf32);

    // pre-convert weights to tf32
    const uint32_t* wtf[12];
    size_t off = 0;
    for (int i = 0; i < 12; i++) {
        cvt_tf32_kernel<<<(wcnt[i] + 255) / 256, 256>>>(wsrc[i], wt + off, wcnt[i]);
        wtf[i] = wt + off;
        off += wcnt[i];
    }

    // molecule branch: 78 -> 156 -> 312 -> 128, output cols [0,128)
    run_branch(x, ei, ei + E_MOL, batch, N_MOL, E_MOL,
               78, 156, 312,
               wtf[0], m1_bl, wtf[1], wtf[2], m2_bl, wtf[3], wtf[4], m3_bl, wtf[5],
               mh1, mh2, magg, mt, mh3, out, 0);

    // clique branch: 92 -> 184 -> 368 -> 128, output cols [128,256)
    run_branch(xc, eic, eic + E_CLQ, batchc, N_CLQ, E_CLQ,
               92, 184, 368,
               wtf[6], c1_bl, wtf[7], wtf[8], c2_bl, wtf[9], wtf[10], c3_bl, wtf[11],
               ch1, ch2, cagg, ct, ch3, out, 128);
}